// round 16
// baseline (speedup 1.0000x reference)
#include <cuda_runtime.h>
#include <cuda_bf16.h>
#include <cuda_fp16.h>
#include <math.h>
#include <stdint.h>

#define NTOK 16384      // B*S
#define HD   512
#define FD   1024
#define NE   16
#define TOPK 2
#define RB   2048       // router blocks (8 tokens each)
#define NPAIR (NTOK*TOPK)
#define ECAP 4096       // fixed per-expert bucket capacity (guarded; max observed ~2200)

// ---------------- scratch (static device globals; no allocation) ----------------
// g_cursor statically initialized to e*ECAP; finalize_kernel resets it after
// snapshotting counts, so every launch (first run, capture, every replay) sees
// identical entry state. Deterministic under CUDA-graph replay.
__device__ int   g_cursor[NE] = {0, 4096, 8192, 12288, 16384, 20480, 24576, 28672,
                                 32768, 36864, 40960, 45056, 49152, 53248, 57344, 61440};
__device__ int   g_counts[NE];
__device__ float g_blockP[RB*NE];
__device__ int   g_pair_tok[NE*ECAP];
__device__ float g_pair_w[NE*ECAP];
__device__ int   g_qhead;          // work-queue head (zeroed in finalize)
__device__ int   g_done1[NE];      // per-expert gemm1 completion (zeroed in finalize)

// fp16 copies
__device__ __half g_xh[NTOK*HD];
__device__ __half g_w1h[NE*FD*HD];
__device__ __half g_w2h[NE*HD*FD];
__device__ __half g_h[(size_t)NE*ECAP*FD];   // bucketed intermediate h (fp16)

// ---------------- helpers ---------------------------------------------------------
__device__ __forceinline__ uint32_t smem_u32(const void* p) {
    uint32_t a;
    asm("{ .reg .u64 t; cvta.to.shared.u64 t, %1; cvt.u32.u64 %0, t; }" : "=r"(a) : "l"(p));
    return a;
}
__device__ __forceinline__ void cp16(uint32_t dst, const __half* src) {
    asm volatile("cp.async.cg.shared.global [%0], [%1], 16;"
                 :: "r"(dst), "l"(__cvta_generic_to_global((const void*)src)) : "memory");
}
#define CP_COMMIT() asm volatile("cp.async.commit_group;" ::: "memory")
#define CP_WAIT(n)  asm volatile("cp.async.wait_group %0;" :: "n"(n) : "memory")

__device__ __forceinline__ void ldm4(uint32_t a, uint32_t& r0, uint32_t& r1, uint32_t& r2, uint32_t& r3) {
    asm volatile("ldmatrix.sync.aligned.m8n8.x4.shared.b16 {%0,%1,%2,%3}, [%4];"
                 : "=r"(r0), "=r"(r1), "=r"(r2), "=r"(r3) : "r"(a));
}
__device__ __forceinline__ void mma16816(float* c, const uint32_t* a, const uint32_t* b) {
    asm volatile("mma.sync.aligned.m16n8k16.row.col.f32.f16.f16.f32 "
                 "{%0,%1,%2,%3}, {%4,%5,%6,%7}, {%8,%9}, {%0,%1,%2,%3};"
                 : "+f"(c[0]), "+f"(c[1]), "+f"(c[2]), "+f"(c[3])
                 : "r"(a[0]), "r"(a[1]), "r"(a[2]), "r"(a[3]), "r"(b[0]), "r"(b[1]));
}

// fast tanh-gelu: tanh(u) = 1 - 2/(e^{2u}+1) via MUFU ex2/rcp (rel err ~2^-21)
__device__ __forceinline__ float gelu_f(float v) {
    float u2 = 1.5957691216057308f * (v + 0.044715f * v * v * v);  // 2*sqrt(2/pi)*(...)
    float ex = __expf(u2);
    float th = 1.0f - __fdividef(2.0f, ex + 1.0f);
    return 0.5f * v * (1.0f + th);   // == jax.nn.gelu approximate=True
}

// GEMM tiling: 128x128 CTA, BK=64, 8 warps (2x4), 64x32 warp tile, 3-stage cp.async
#define BM 128
#define BN 128
#define BK 64
#define PITCH 144                 // 128B data + 16B pad (ldmatrix conflict-free)
#define TILEB  (BM*PITCH)         // 18432
#define STAGE  (2*TILEB)          // A + B = 36864
#define NSTAGE 3
#define SMEM_DYN (NSTAGE*STAGE)   // 110592

// fragment loads for one kk-step into buffer bf
#define LOAD_FRAGS(bf, st, kkb)                                                     \
    do {                                                                            \
        _Pragma("unroll")                                                           \
        for (int i = 0; i < 4; ++i)                                                 \
            ldm4((st) + oa[i] + (kkb), A[bf][i][0], A[bf][i][1], A[bf][i][2], A[bf][i][3]); \
        _Pragma("unroll")                                                           \
        for (int jj = 0; jj < 2; ++jj) {                                            \
            uint32_t r0, r1, r2, r3;                                                \
            ldm4((st) + ob[jj] + (kkb), r0, r1, r2, r3);                            \
            Bf[bf][2*jj][0] = r0; Bf[bf][2*jj+1][0] = r1;                           \
            Bf[bf][2*jj][1] = r2; Bf[bf][2*jj+1][1] = r3;                           \
        }                                                                           \
    } while (0)

#define MMAS(kk)                                                                    \
    do {                                                                            \
        _Pragma("unroll")                                                           \
        for (int i = 0; i < 4; ++i)                                                 \
            _Pragma("unroll")                                                       \
            for (int j = 0; j < 4; ++j)                                             \
                mma16816(acc[i][j], A[(kk)&1][i], Bf[(kk)&1][j]);                   \
    } while (0)

// ---------------- prep mega-kernel: router+scatter+x-fp16 | W-convert | y-zero ----
#define N4  ((NE*FD*HD)/4)        // 2097152 float4 per weight tensor
#define Y4  ((NTOK*HD)/4)         // 2097152 float4 of y
#define PREP_BLOCKS (RB + (2*N4)/256 + Y4/256)   // 26624

__global__ void __launch_bounds__(256) prep_kernel(const float* __restrict__ x,
                                                   const float* __restrict__ Wr,
                                                   const float4* __restrict__ w1f,
                                                   const float4* __restrict__ w2f,
                                                   __half2* __restrict__ w1h,
                                                   __half2* __restrict__ w2h,
                                                   float4* __restrict__ y4)
{
    const int b = blockIdx.x;
    if (b >= RB) {
        int idx = (b - RB) * 256 + threadIdx.x;
        if (idx < 2*N4) {
            const float4* src; __half2* dst; int j = idx;
            if (idx < N4) { src = w1f; dst = w1h; }
            else          { src = w2f; dst = w2h; j = idx - N4; }
            float4 v = src[j];
            dst[2*j]   = __floats2half2_rn(v.x, v.y);
            dst[2*j+1] = __floats2half2_rn(v.z, v.w);
        } else {
            int j = idx - 2*N4;
            y4[j] = make_float4(0.f, 0.f, 0.f, 0.f);
        }
        return;
    }

    // ---- router domain: 8 tokens per block ----
    __shared__ float sP[8][16];
    const int warp = threadIdx.x >> 5;
    const int lane = threadIdx.x & 31;
    const int t = b * 8 + warp;

    float acc[NE];
#pragma unroll
    for (int e = 0; e < NE; e++) acc[e] = 0.f;

    const float* xr = x + (size_t)t * HD;
    __half* xhr = g_xh + (size_t)t * HD;
    for (int i = lane; i < HD; i += 32) {
        float xv = xr[i];
        xhr[i] = __float2half_rn(xv);
#pragma unroll
        for (int e = 0; e < NE; e++) acc[e] = fmaf(xv, Wr[e*HD + i], acc[e]);
    }
#pragma unroll
    for (int e = 0; e < NE; e++) {
#pragma unroll
        for (int o = 16; o > 0; o >>= 1)
            acc[e] += __shfl_xor_sync(0xffffffffu, acc[e], o);
    }
    if (lane == 0) {
        float m = acc[0];
#pragma unroll
        for (int e = 1; e < NE; e++) m = fmaxf(m, acc[e]);
        float pr[NE]; float s = 0.f;
#pragma unroll
        for (int e = 0; e < NE; e++) { pr[e] = __expf(acc[e] - m); s += pr[e]; }
        float inv = 1.f / s;
#pragma unroll
        for (int e = 0; e < NE; e++) sP[warp][e] = pr[e] * inv;

        int i0 = 0; float v0 = acc[0];
#pragma unroll
        for (int e = 1; e < NE; e++) if (acc[e] > v0) { v0 = acc[e]; i0 = e; }
        float v1 = -3.4e38f; int i1 = -1;
#pragma unroll
        for (int e = 0; e < NE; e++) if (e != i0 && acc[e] > v1) { v1 = acc[e]; i1 = e; }

        float e1 = __expf(v1 - v0);
        float w0 = 1.f / (1.f + e1);
        float w1 = e1 / (1.f + e1);

        int b0 = i0 * ECAP;
        int p0 = atomicAdd(&g_cursor[i0], 1) - b0; if (p0 >= ECAP) p0 = ECAP - 1;
        g_pair_tok[b0 + p0] = t;  g_pair_w[b0 + p0] = w0;
        int b1 = i1 * ECAP;
        int p1 = atomicAdd(&g_cursor[i1], 1) - b1; if (p1 >= ECAP) p1 = ECAP - 1;
        g_pair_tok[b1 + p1] = t;  g_pair_w[b1 + p1] = w1;
    }
    __syncthreads();
    if (threadIdx.x < NE) {
        float s = 0.f;
#pragma unroll
        for (int w = 0; w < 8; w++) s += sP[w][threadIdx.x];   // fixed order: deterministic
        g_blockP[b * NE + threadIdx.x] = s;
    }
}

// ---------------- finalize: l_aux + counts + cursor/queue reset ---------------------
__global__ void __launch_bounds__(1024) finalize_kernel(float* __restrict__ out, int out_size)
{
    __shared__ float part[1024];
    __shared__ float sPe[NE];
    __shared__ int   sCnt[NE];
    const int t = threadIdx.x;
    const int e = t & 15, c = t >> 4;
    float s = 0.f;
    for (int b = c*32; b < c*32 + 32; ++b) s += g_blockP[b*NE + e];
    part[t] = s;
    if (t < NE) {
        int cnt = g_cursor[t] - t * ECAP;
        sCnt[t] = cnt;
        g_counts[t] = (cnt > ECAP) ? ECAP : cnt;   // clamped for gemms
        g_cursor[t] = t * ECAP;                    // reset for next graph replay
        g_done1[t] = 0;                            // reset gemm1 completion counters
    }
    if (t == 0) g_qhead = 0;                       // reset work queue
    __syncthreads();
    if (t < NE) {
        float s2 = 0.f;
#pragma unroll
        for (int cc = 0; cc < 64; ++cc) s2 += part[cc*16 + t];  // fixed order
        sPe[t] = s2;
    }
    __syncthreads();
    if (t == 0) {
        float laux = 0.f;
#pragma unroll
        for (int ee = 0; ee < NE; ++ee) {
            float f = (float)sCnt[ee] * (1.0f / (float)(NTOK * TOPK));
            float P = sPe[ee] * (1.0f / (float)NTOK);
            laux += f * P;
        }
        laux *= (float)NE;
        if (out_size > NTOK * HD) out[NTOK * HD] = laux;
    }
}

// ======================= gemm1 tile body: h = gelu(Xg @ W1^T + b1) ================
__device__ __forceinline__ void g1_body(uint32_t sb, int* sTok,
                                        int e, int n0, int m0, int count,
                                        const float* __restrict__ b1)
{
    const int tid = threadIdx.x, wid = tid >> 5, lane = tid & 31;
    const int offset = e * ECAP;
    if (tid < BM) {
        int m = m0 + tid; if (m > count - 1) m = count - 1;
        sTok[tid] = g_pair_tok[offset + m];
    }
    __syncthreads();

    const int lrow = tid >> 1, lsg = (tid & 1) * 4;

    auto load_stage = [&](int buf, int kc) {
        uint32_t base = sb + buf*STAGE;
        {
            size_t ga = (size_t)sTok[lrow] * HD + kc + lsg*8;
            uint32_t d = base + lrow*PITCH + lsg*16;
            cp16(d, g_xh+ga); cp16(d+16, g_xh+ga+8); cp16(d+32, g_xh+ga+16); cp16(d+48, g_xh+ga+24);
        }
        {
            size_t gb = ((size_t)e * FD + n0 + lrow) * HD + kc + lsg*8;
            uint32_t d = base + TILEB + lrow*PITCH + lsg*16;
            cp16(d, g_w1h+gb); cp16(d+16, g_w1h+gb+8); cp16(d+32, g_w1h+gb+16); cp16(d+48, g_w1h+gb+24);
        }
        CP_COMMIT();
    };

    const int wm = (wid >> 2) * 64, wn = (wid & 3) * 32;
    const int lr = lane & 15, lcb = (lane >> 4) * 16;

    uint32_t oa[4], ob[2];
#pragma unroll
    for (int i = 0; i < 4; ++i)  oa[i] = (wm + i*16 + lr)*PITCH + lcb;
#pragma unroll
    for (int jj = 0; jj < 2; ++jj) ob[jj] = TILEB + (wn + jj*16 + lr)*PITCH + lcb;

    float acc[4][4][4];
#pragma unroll
    for (int i = 0; i < 4; i++)
#pragma unroll
        for (int j = 0; j < 4; j++)
#pragma unroll
            for (int q = 0; q < 4; q++) acc[i][j][q] = 0.f;

    uint32_t A[2][4][4], Bf[2][4][2];

    const int NIT = HD / BK;   // 8
    load_stage(0, 0); load_stage(1, BK); load_stage(2, 2*BK);
    for (int it = 0; it < NIT; ++it) {
        CP_WAIT(2);
        __syncthreads();
        const uint32_t st = sb + (it % 3)*STAGE;
        LOAD_FRAGS(0, st, 0);
        LOAD_FRAGS(1, st, 32);  MMAS(0);
        LOAD_FRAGS(0, st, 64);  MMAS(1);
        LOAD_FRAGS(1, st, 96);  MMAS(2);
        __syncthreads();
        if (it + 3 < NIT) load_stage(it % 3, (it + 3) * BK); else CP_COMMIT();
        MMAS(3);
    }

#pragma unroll
    for (int i = 0; i < 4; ++i) {
#pragma unroll
        for (int j = 0; j < 4; ++j) {
            int col = n0 + wn + j*8 + (lane & 3)*2;
            float bb0 = __ldg(&b1[e*FD + col]);
            float bb1 = __ldg(&b1[e*FD + col + 1]);
#pragma unroll
            for (int half = 0; half < 2; ++half) {
                int m  = wm + i*16 + (lane >> 2) + half*8;
                int gm = m0 + m;
                if (gm < count) {
                    float v0 = gelu_f(acc[i][j][half*2]     + bb0);
                    float v1 = gelu_f(acc[i][j][half*2 + 1] + bb1);
                    size_t o = (size_t)(offset + gm) * FD + col;
                    *(__half2*)(g_h + o) = __floats2half2_rn(v0, v1);
                }
            }
        }
    }
}

// ======================= gemm2 tile body: y += w * (h @ W2^T + b2) ================
__device__ __forceinline__ void g2_body(uint32_t sb, int* sTok, float* sW,
                                        int e, int n0, int m0, int count,
                                        const float* __restrict__ b2,
                                        float* __restrict__ y)
{
    const int tid = threadIdx.x, wid = tid >> 5, lane = tid & 31;
    const int offset = e * ECAP;
    if (tid < BM) {
        int m = m0 + tid; if (m > count - 1) m = count - 1;
        sTok[tid] = g_pair_tok[offset + m];
        sW[tid]   = g_pair_w[offset + m];
    }
    __syncthreads();

    const int lrow = tid >> 1, lsg = (tid & 1) * 4;
    int ar = m0 + lrow; if (ar > count - 1) ar = count - 1;
    const size_t arow = (size_t)(offset + ar) * FD;

    auto load_stage = [&](int buf, int kc) {
        uint32_t base = sb + buf*STAGE;
        {
            size_t ga = arow + kc + lsg*8;
            uint32_t d = base + lrow*PITCH + lsg*16;
            cp16(d, g_h+ga); cp16(d+16, g_h+ga+8); cp16(d+32, g_h+ga+16); cp16(d+48, g_h+ga+24);
        }
        {
            size_t gb = ((size_t)e * HD + n0 + lrow) * FD + kc + lsg*8;
            uint32_t d = base + TILEB + lrow*PITCH + lsg*16;
            cp16(d, g_w2h+gb); cp16(d+16, g_w2h+gb+8); cp16(d+32, g_w2h+gb+16); cp16(d+48, g_w2h+gb+24);
        }
        CP_COMMIT();
    };

    const int wm = (wid >> 2) * 64, wn = (wid & 3) * 32;
    const int lr = lane & 15, lcb = (lane >> 4) * 16;

    uint32_t oa[4], ob[2];
#pragma unroll
    for (int i = 0; i < 4; ++i)  oa[i] = (wm + i*16 + lr)*PITCH + lcb;
#pragma unroll
    for (int jj = 0; jj < 2; ++jj) ob[jj] = TILEB + (wn + jj*16 + lr)*PITCH + lcb;

    float acc[4][4][4];
#pragma unroll
    for (int i = 0; i < 4; i++)
#pragma unroll
        for (int j = 0; j < 4; j++)
#pragma unroll
            for (int q = 0; q < 4; q++) acc[i][j][q] = 0.f;

    uint32_t A[2][4][4], Bf[2][4][2];

    const int NIT = FD / BK;   // 16
    load_stage(0, 0); load_stage(1, BK); load_stage(2, 2*BK);
    for (int it = 0; it < NIT; ++it) {
        CP_WAIT(2);
        __syncthreads();
        const uint32_t st = sb + (it % 3)*STAGE;
        LOAD_FRAGS(0, st, 0);
        LOAD_FRAGS(1, st, 32);  MMAS(0);
        LOAD_FRAGS(0, st, 64);  MMAS(1);
        LOAD_FRAGS(1, st, 96);  MMAS(2);
        __syncthreads();
        if (it + 3 < NIT) load_stage(it % 3, (it + 3) * BK); else CP_COMMIT();
        MMAS(3);
    }

#pragma unroll
    for (int i = 0; i < 4; ++i) {
#pragma unroll
        for (int j = 0; j < 4; ++j) {
            int col = n0 + wn + j*8 + (lane & 3)*2;
            float bb0 = __ldg(&b2[e*HD + col]);
            float bb1 = __ldg(&b2[e*HD + col + 1]);
#pragma unroll
            for (int half = 0; half < 2; ++half) {
                int m  = wm + i*16 + (lane >> 2) + half*8;
                int gm = m0 + m;
                if (gm < count) {
                    int   tok = sTok[m];
                    float w   = sW[m];
                    float* dst = y + (size_t)tok * HD + col;
                    atomicAdd(&dst[0], w * (acc[i][j][half*2]     + bb0));
                    atomicAdd(&dst[1], w * (acc[i][j][half*2 + 1] + bb1));
                }
            }
        }
    }
}

// ======================= fused persistent GEMM scheduler ===========================
#define G1_ITEMS 4096            // 16 experts x 8 n-blocks x 32 m-blocks
#define G1_PER_E 256
#define TOTAL_ITEMS 6144         // + 16 x 4 x 32 gemm2 items
#define PERSIST_CTAS 296         // 2 per SM x 148 SMs (any smaller SM count still correct)

__global__ void __launch_bounds__(256) fused_gemm(const float* __restrict__ b1,
                                                  const float* __restrict__ b2,
                                                  float* __restrict__ y)
{
    extern __shared__ char smem[];
    __shared__ int   sTok[BM];
    __shared__ float sW[BM];
    __shared__ int   sItem;
    const uint32_t sb = smem_u32(smem);
    const int tid = threadIdx.x;

    for (;;) {
        if (tid == 0) sItem = atomicAdd(&g_qhead, 1);
        __syncthreads();
        const int item = sItem;
        __syncthreads();                       // protect sItem until all have read it
        if (item >= TOTAL_ITEMS) return;

        if (item < G1_ITEMS) {
            const int e  = item >> 8, r = item & 255;
            const int n0 = (r >> 5) << 7, m0 = (r & 31) << 7;
            const int count = g_counts[e];
            if (m0 < count) {
                g1_body(sb, sTok, e, n0, m0, count, b1);
                __threadfence();               // publish h before signaling
                __syncthreads();
            }
            if (tid == 0) atomicAdd(&g_done1[e], 1);   // no-ops count too (target 256)
        } else {
            const int j  = item - G1_ITEMS;
            const int e  = j >> 7, r = j & 127;
            const int n0 = (r >> 5) << 7, m0 = (r & 31) << 7;
            const int count = g_counts[e];
            if (m0 < count) {
                if (tid == 0) {
                    while (*(volatile int*)&g_done1[e] < G1_PER_E) __nanosleep(100);
                }
                __syncthreads();
                __threadfence();               // acquire: order h reads after flag
                g2_body(sb, sTok, sW, e, n0, m0, count, b2, y);
            }
        }
    }
}

// ---------------- launch -----------------------------------------------------------
extern "C" void kernel_launch(void* const* d_in, const int* in_sizes, int n_in,
                              void* d_out, int out_size)
{
    const float* x  = (const float*)d_in[0];
    const float* Wr = (const float*)d_in[1];
    const float* W1 = (const float*)d_in[2];
    const float* b1 = (const float*)d_in[3];
    const float* W2 = (const float*)d_in[4];
    const float* b2 = (const float*)d_in[5];
    float* y = (float*)d_out;

    cudaFuncSetAttribute(fused_gemm, cudaFuncAttributeMaxDynamicSharedMemorySize, SMEM_DYN);

    {
        __half2 *w1h, *w2h;
        cudaGetSymbolAddress((void**)&w1h, g_w1h);
        cudaGetSymbolAddress((void**)&w2h, g_w2h);
        prep_kernel<<<PREP_BLOCKS, 256>>>(x, Wr, (const float4*)W1, (const float4*)W2,
                                          w1h, w2h, (float4*)d_out);                 // 1
    }
    finalize_kernel<<<1, 1024>>>(y, out_size);                                       // 2 (l_aux + counts + queue reset)
    fused_gemm<<<PERSIST_CTAS, 256, SMEM_DYN>>>(b1, b2, y);                          // 3 (persistent gemm1+gemm2)
}

// round 17
// speedup vs baseline: 1.1714x; 1.1714x over previous
#include <cuda_runtime.h>
#include <cuda_bf16.h>
#include <cuda_fp16.h>
#include <math.h>
#include <stdint.h>

#define NTOK 16384      // B*S
#define HD   512
#define FD   1024
#define NE   16
#define TOPK 2
#define RB   2048       // router blocks (8 tokens each)
#define NPAIR (NTOK*TOPK)
#define ECAP 4096       // fixed per-expert bucket capacity (guarded; max observed ~2200)

// ---------------- scratch (static device globals; no allocation) ----------------
// g_cursor statically initialized to e*ECAP; finalize_kernel resets it after
// snapshotting counts, so every launch (first run, capture, every replay) sees
// identical entry state. Deterministic under CUDA-graph replay.
__device__ int   g_cursor[NE] = {0, 4096, 8192, 12288, 16384, 20480, 24576, 28672,
                                 32768, 36864, 40960, 45056, 49152, 53248, 57344, 61440};
__device__ int   g_counts[NE];
__device__ float g_blockP[RB*NE];
__device__ int   g_pair_tok[NE*ECAP];
__device__ float g_pair_w[NE*ECAP];

// fp16 copies
__device__ __half g_xh[NTOK*HD];
__device__ __half g_w1h[NE*FD*HD];
__device__ __half g_w2h[NE*HD*FD];
__device__ __half g_h[(size_t)NE*ECAP*FD];   // bucketed intermediate h (fp16)

// ---------------- helpers ---------------------------------------------------------
__device__ __forceinline__ uint32_t smem_u32(const void* p) {
    uint32_t a;
    asm("{ .reg .u64 t; cvta.to.shared.u64 t, %1; cvt.u32.u64 %0, t; }" : "=r"(a) : "l"(p));
    return a;
}
__device__ __forceinline__ void cp16(uint32_t dst, const __half* src) {
    asm volatile("cp.async.cg.shared.global [%0], [%1], 16;"
                 :: "r"(dst), "l"(__cvta_generic_to_global((const void*)src)) : "memory");
}
#define CP_COMMIT() asm volatile("cp.async.commit_group;" ::: "memory")
#define CP_WAIT(n)  asm volatile("cp.async.wait_group %0;" :: "n"(n) : "memory")

__device__ __forceinline__ void ldm4(uint32_t a, uint32_t& r0, uint32_t& r1, uint32_t& r2, uint32_t& r3) {
    asm volatile("ldmatrix.sync.aligned.m8n8.x4.shared.b16 {%0,%1,%2,%3}, [%4];"
                 : "=r"(r0), "=r"(r1), "=r"(r2), "=r"(r3) : "r"(a));
}
__device__ __forceinline__ void mma16816(float* c, const uint32_t* a, const uint32_t* b) {
    asm volatile("mma.sync.aligned.m16n8k16.row.col.f32.f16.f16.f32 "
                 "{%0,%1,%2,%3}, {%4,%5,%6,%7}, {%8,%9}, {%0,%1,%2,%3};"
                 : "+f"(c[0]), "+f"(c[1]), "+f"(c[2]), "+f"(c[3])
                 : "r"(a[0]), "r"(a[1]), "r"(a[2]), "r"(a[3]), "r"(b[0]), "r"(b[1]));
}

// fast tanh-gelu: tanh(u) = 1 - 2/(e^{2u}+1) via MUFU ex2/rcp (rel err ~2^-21)
__device__ __forceinline__ float gelu_f(float v) {
    float u2 = 1.5957691216057308f * (v + 0.044715f * v * v * v);  // 2*sqrt(2/pi)*(...)
    float ex = __expf(u2);
    float th = 1.0f - __fdividef(2.0f, ex + 1.0f);
    return 0.5f * v * (1.0f + th);   // == jax.nn.gelu approximate=True
}

// GEMM tiling: 128x128 CTA, BK=64, 8 warps (2x4), 64x32 warp tile, 3-stage cp.async
#define BM 128
#define BN 128
#define BK 64
#define PITCH 144                 // 128B data + 16B pad (ldmatrix conflict-free)
#define TILEB  (BM*PITCH)         // 18432
#define STAGE  (2*TILEB)          // A + B = 36864
#define NSTAGE 3
#define SMEM_DYN (NSTAGE*STAGE)   // 110592

// fragment loads for one kk-step into buffer bf
#define LOAD_FRAGS(bf, st, kkb)                                                     \
    do {                                                                            \
        _Pragma("unroll")                                                           \
        for (int i = 0; i < 4; ++i)                                                 \
            ldm4((st) + oa[i] + (kkb), A[bf][i][0], A[bf][i][1], A[bf][i][2], A[bf][i][3]); \
        _Pragma("unroll")                                                           \
        for (int jj = 0; jj < 2; ++jj) {                                            \
            uint32_t r0, r1, r2, r3;                                                \
            ldm4((st) + ob[jj] + (kkb), r0, r1, r2, r3);                            \
            Bf[bf][2*jj][0] = r0; Bf[bf][2*jj+1][0] = r1;                           \
            Bf[bf][2*jj][1] = r2; Bf[bf][2*jj+1][1] = r3;                           \
        }                                                                           \
    } while (0)

#define MMAS(kk)                                                                    \
    do {                                                                            \
        _Pragma("unroll")                                                           \
        for (int i = 0; i < 4; ++i)                                                 \
            _Pragma("unroll")                                                       \
            for (int j = 0; j < 4; ++j)                                             \
                mma16816(acc[i][j], A[(kk)&1][i], Bf[(kk)&1][j]);                   \
    } while (0)

// ---------------- prep mega-kernel: router | W-convert (MLP=4) | y-zero (MLP=4) ----
#define N4  ((NE*FD*HD)/4)        // 2097152 float4 per weight tensor
#define Y4  ((NTOK*HD)/4)         // 2097152 float4 of y
#define CONV_BLOCKS 4096          // 2*N4 elements / (256 thr * 4 per thr)
#define CONV_T (CONV_BLOCKS*256)  // 1048576 threads; 2*N4 = 4*CONV_T
#define ZERO_BLOCKS 2048          // Y4 / (256*4)
#define ZERO_T (ZERO_BLOCKS*256)  // 524288; Y4 = 4*ZERO_T
#define PREP_BLOCKS (RB + CONV_BLOCKS + ZERO_BLOCKS)   // 8192

__global__ void __launch_bounds__(256) prep_kernel(const float* __restrict__ x,
                                                   const float* __restrict__ Wr,
                                                   const float4* __restrict__ w1f,
                                                   const float4* __restrict__ w2f,
                                                   __half2* __restrict__ w1h,
                                                   __half2* __restrict__ w2h,
                                                   float4* __restrict__ y4)
{
    const int b = blockIdx.x;
    if (b >= RB + CONV_BLOCKS) {
        // ---- y-zero domain: 4 strided float4 per thread ----
        int idx = (b - RB - CONV_BLOCKS) * 256 + threadIdx.x;
        float4 z = make_float4(0.f, 0.f, 0.f, 0.f);
#pragma unroll
        for (int q = 0; q < 4; ++q) y4[idx + q*ZERO_T] = z;
        return;
    }
    if (b >= RB) {
        // ---- convert domain: 4 strided float4 per thread (MLP=4) ----
        int idx = (b - RB) * 256 + threadIdx.x;
        float4 v[4];
#pragma unroll
        for (int q = 0; q < 4; ++q) {
            int j = idx + q*CONV_T;
            v[q] = (j < N4) ? w1f[j] : w2f[j - N4];
        }
#pragma unroll
        for (int q = 0; q < 4; ++q) {
            int j = idx + q*CONV_T;
            __half2* dst; int jj = j;
            if (j < N4) { dst = w1h; }
            else        { dst = w2h; jj = j - N4; }
            dst[2*jj]   = __floats2half2_rn(v[q].x, v[q].y);
            dst[2*jj+1] = __floats2half2_rn(v[q].z, v[q].w);
        }
        return;
    }

    // ---- router domain: 8 tokens per block ----
    __shared__ float sP[8][16];
    const int warp = threadIdx.x >> 5;
    const int lane = threadIdx.x & 31;
    const int t = b * 8 + warp;

    float acc[NE];
#pragma unroll
    for (int e = 0; e < NE; e++) acc[e] = 0.f;

    const float* xr = x + (size_t)t * HD;
    __half* xhr = g_xh + (size_t)t * HD;
    for (int i = lane; i < HD; i += 32) {
        float xv = xr[i];
        xhr[i] = __float2half_rn(xv);
#pragma unroll
        for (int e = 0; e < NE; e++) acc[e] = fmaf(xv, Wr[e*HD + i], acc[e]);
    }
#pragma unroll
    for (int e = 0; e < NE; e++) {
#pragma unroll
        for (int o = 16; o > 0; o >>= 1)
            acc[e] += __shfl_xor_sync(0xffffffffu, acc[e], o);
    }
    if (lane == 0) {
        float m = acc[0];
#pragma unroll
        for (int e = 1; e < NE; e++) m = fmaxf(m, acc[e]);
        float pr[NE]; float s = 0.f;
#pragma unroll
        for (int e = 0; e < NE; e++) { pr[e] = __expf(acc[e] - m); s += pr[e]; }
        float inv = 1.f / s;
#pragma unroll
        for (int e = 0; e < NE; e++) sP[warp][e] = pr[e] * inv;

        int i0 = 0; float v0 = acc[0];
#pragma unroll
        for (int e = 1; e < NE; e++) if (acc[e] > v0) { v0 = acc[e]; i0 = e; }
        float v1 = -3.4e38f; int i1 = -1;
#pragma unroll
        for (int e = 0; e < NE; e++) if (e != i0 && acc[e] > v1) { v1 = acc[e]; i1 = e; }

        float e1 = __expf(v1 - v0);
        float w0 = 1.f / (1.f + e1);
        float w1 = e1 / (1.f + e1);

        int b0 = i0 * ECAP;
        int p0 = atomicAdd(&g_cursor[i0], 1) - b0; if (p0 >= ECAP) p0 = ECAP - 1;
        g_pair_tok[b0 + p0] = t;  g_pair_w[b0 + p0] = w0;
        int b1 = i1 * ECAP;
        int p1 = atomicAdd(&g_cursor[i1], 1) - b1; if (p1 >= ECAP) p1 = ECAP - 1;
        g_pair_tok[b1 + p1] = t;  g_pair_w[b1 + p1] = w1;
    }
    __syncthreads();
    if (threadIdx.x < NE) {
        float s = 0.f;
#pragma unroll
        for (int w = 0; w < 8; w++) s += sP[w][threadIdx.x];   // fixed order: deterministic
        g_blockP[b * NE + threadIdx.x] = s;
    }
}

// ---------------- finalize: l_aux + counts snapshot + cursor reset ------------------
__global__ void __launch_bounds__(1024) finalize_kernel(float* __restrict__ out, int out_size)
{
    __shared__ float part[1024];
    __shared__ float sPe[NE];
    __shared__ int   sCnt[NE];
    const int t = threadIdx.x;
    const int e = t & 15, c = t >> 4;
    float s = 0.f;
    for (int b = c*32; b < c*32 + 32; ++b) s += g_blockP[b*NE + e];
    part[t] = s;
    if (t < NE) {
        int cnt = g_cursor[t] - t * ECAP;
        sCnt[t] = cnt;
        g_counts[t] = (cnt > ECAP) ? ECAP : cnt;   // clamped for gemms
        g_cursor[t] = t * ECAP;                    // reset for next graph replay
    }
    __syncthreads();
    if (t < NE) {
        float s2 = 0.f;
#pragma unroll
        for (int cc = 0; cc < 64; ++cc) s2 += part[cc*16 + t];  // fixed order
        sPe[t] = s2;
    }
    __syncthreads();
    if (t == 0) {
        float laux = 0.f;
#pragma unroll
        for (int ee = 0; ee < NE; ++ee) {
            float f = (float)sCnt[ee] * (1.0f / (float)(NTOK * TOPK));
            float P = sPe[ee] * (1.0f / (float)NTOK);
            laux += f * P;
        }
        laux *= (float)NE;
        if (out_size > NTOK * HD) out[NTOK * HD] = laux;
    }
}

// ======================= HMMA GEMM1: h = gelu(Xg @ W1^T + b1) =====================
__global__ void __launch_bounds__(256, 1) gemm1_mma(const float* __restrict__ b1)
{
    extern __shared__ char smem[];
    const int e = blockIdx.z;
    const int count = g_counts[e];
    const int m0 = blockIdx.x * BM;
    if (m0 >= count) return;
    const int offset = e * ECAP;
    const int n0 = blockIdx.y * BN;
    const int tid = threadIdx.x, wid = tid >> 5, lane = tid & 31;

    __shared__ int sTok[BM];
    if (tid < BM) {
        int m = m0 + tid; if (m > count - 1) m = count - 1;
        sTok[tid] = g_pair_tok[offset + m];
    }
    __syncthreads();
    const uint32_t sb = smem_u32(smem);

    const int lrow = tid >> 1, lsg = (tid & 1) * 4;

    auto load_stage = [&](int buf, int kc) {
        uint32_t base = sb + buf*STAGE;
        {
            size_t ga = (size_t)sTok[lrow] * HD + kc + lsg*8;
            uint32_t d = base + lrow*PITCH + lsg*16;
            cp16(d, g_xh+ga); cp16(d+16, g_xh+ga+8); cp16(d+32, g_xh+ga+16); cp16(d+48, g_xh+ga+24);
        }
        {
            size_t gb = ((size_t)e * FD + n0 + lrow) * HD + kc + lsg*8;
            uint32_t d = base + TILEB + lrow*PITCH + lsg*16;
            cp16(d, g_w1h+gb); cp16(d+16, g_w1h+gb+8); cp16(d+32, g_w1h+gb+16); cp16(d+48, g_w1h+gb+24);
        }
        CP_COMMIT();
    };

    const int wm = (wid >> 2) * 64, wn = (wid & 3) * 32;
    const int lr = lane & 15, lcb = (lane >> 4) * 16;

    uint32_t oa[4], ob[2];
#pragma unroll
    for (int i = 0; i < 4; ++i)  oa[i] = (wm + i*16 + lr)*PITCH + lcb;
#pragma unroll
    for (int jj = 0; jj < 2; ++jj) ob[jj] = TILEB + (wn + jj*16 + lr)*PITCH + lcb;

    float acc[4][4][4];
#pragma unroll
    for (int i = 0; i < 4; i++)
#pragma unroll
        for (int j = 0; j < 4; j++)
#pragma unroll
            for (int q = 0; q < 4; q++) acc[i][j][q] = 0.f;

    uint32_t A[2][4][4], Bf[2][4][2];

    const int NIT = HD / BK;   // 8
    load_stage(0, 0); load_stage(1, BK); load_stage(2, 2*BK);
    for (int it = 0; it < NIT; ++it) {
        CP_WAIT(2);
        __syncthreads();
        const uint32_t st = sb + (it % 3)*STAGE;
        LOAD_FRAGS(0, st, 0);
        LOAD_FRAGS(1, st, 32);  MMAS(0);
        LOAD_FRAGS(0, st, 64);  MMAS(1);
        LOAD_FRAGS(1, st, 96);  MMAS(2);
        __syncthreads();        // all warps done reading this stage's SMEM
        if (it + 3 < NIT) load_stage(it % 3, (it + 3) * BK); else CP_COMMIT();
        MMAS(3);                // overlap last MMA block with next-stage load issue
    }

    // epilogue: bias + fast gelu + fp16 store
#pragma unroll
    for (int i = 0; i < 4; ++i) {
#pragma unroll
        for (int j = 0; j < 4; ++j) {
            int col = n0 + wn + j*8 + (lane & 3)*2;
            float bb0 = __ldg(&b1[e*FD + col]);
            float bb1 = __ldg(&b1[e*FD + col + 1]);
#pragma unroll
            for (int half = 0; half < 2; ++half) {
                int m  = wm + i*16 + (lane >> 2) + half*8;
                int gm = m0 + m;
                if (gm < count) {
                    float v0 = gelu_f(acc[i][j][half*2]     + bb0);
                    float v1 = gelu_f(acc[i][j][half*2 + 1] + bb1);
                    size_t o = (size_t)(offset + gm) * FD + col;
                    *(__half2*)(g_h + o) = __floats2half2_rn(v0, v1);
                }
            }
        }
    }
}

// ======================= HMMA GEMM2: y += w * (h @ W2^T + b2) =====================
__global__ void __launch_bounds__(256, 1) gemm2_mma(const float* __restrict__ b2,
                                                    float* __restrict__ y)
{
    extern __shared__ char smem[];
    const int e = blockIdx.z;
    const int count = g_counts[e];
    const int m0 = blockIdx.x * BM;
    if (m0 >= count) return;
    const int offset = e * ECAP;
    const int n0 = blockIdx.y * BN;
    const int tid = threadIdx.x, wid = tid >> 5, lane = tid & 31;

    __shared__ int   sTok[BM];
    __shared__ float sW[BM];
    if (tid < BM) {
        int m = m0 + tid; if (m > count - 1) m = count - 1;
        sTok[tid] = g_pair_tok[offset + m];
        sW[tid]   = g_pair_w[offset + m];
    }
    __syncthreads();
    const uint32_t sb = smem_u32(smem);

    const int lrow = tid >> 1, lsg = (tid & 1) * 4;
    int ar = m0 + lrow; if (ar > count - 1) ar = count - 1;
    const size_t arow = (size_t)(offset + ar) * FD;

    auto load_stage = [&](int buf, int kc) {
        uint32_t base = sb + buf*STAGE;
        {
            size_t ga = arow + kc + lsg*8;
            uint32_t d = base + lrow*PITCH + lsg*16;
            cp16(d, g_h+ga); cp16(d+16, g_h+ga+8); cp16(d+32, g_h+ga+16); cp16(d+48, g_h+ga+24);
        }
        {
            size_t gb = ((size_t)e * HD + n0 + lrow) * FD + kc + lsg*8;
            uint32_t d = base + TILEB + lrow*PITCH + lsg*16;
            cp16(d, g_w2h+gb); cp16(d+16, g_w2h+gb+8); cp16(d+32, g_w2h+gb+16); cp16(d+48, g_w2h+gb+24);
        }
        CP_COMMIT();
    };

    const int wm = (wid >> 2) * 64, wn = (wid & 3) * 32;
    const int lr = lane & 15, lcb = (lane >> 4) * 16;

    uint32_t oa[4], ob[2];
#pragma unroll
    for (int i = 0; i < 4; ++i)  oa[i] = (wm + i*16 + lr)*PITCH + lcb;
#pragma unroll
    for (int jj = 0; jj < 2; ++jj) ob[jj] = TILEB + (wn + jj*16 + lr)*PITCH + lcb;

    float acc[4][4][4];
#pragma unroll
    for (int i = 0; i < 4; i++)
#pragma unroll
        for (int j = 0; j < 4; j++)
#pragma unroll
            for (int q = 0; q < 4; q++) acc[i][j][q] = 0.f;

    uint32_t A[2][4][4], Bf[2][4][2];

    const int NIT = FD / BK;   // 16
    load_stage(0, 0); load_stage(1, BK); load_stage(2, 2*BK);
    for (int it = 0; it < NIT; ++it) {
        CP_WAIT(2);
        __syncthreads();
        const uint32_t st = sb + (it % 3)*STAGE;
        LOAD_FRAGS(0, st, 0);
        LOAD_FRAGS(1, st, 32);  MMAS(0);
        LOAD_FRAGS(0, st, 64);  MMAS(1);
        LOAD_FRAGS(1, st, 96);  MMAS(2);
        __syncthreads();
        if (it + 3 < NIT) load_stage(it % 3, (it + 3) * BK); else CP_COMMIT();
        MMAS(3);
    }

    // epilogue: weighted atomic accumulate into y (2 commutative contributions/elem)
#pragma unroll
    for (int i = 0; i < 4; ++i) {
#pragma unroll
        for (int j = 0; j < 4; ++j) {
            int col = n0 + wn + j*8 + (lane & 3)*2;
            float bb0 = __ldg(&b2[e*HD + col]);
            float bb1 = __ldg(&b2[e*HD + col + 1]);
#pragma unroll
            for (int half = 0; half < 2; ++half) {
                int m  = wm + i*16 + (lane >> 2) + half*8;
                int gm = m0 + m;
                if (gm < count) {
                    int   tok = sTok[m];
                    float w   = sW[m];
                    float* dst = y + (size_t)tok * HD + col;
                    atomicAdd(&dst[0], w * (acc[i][j][half*2]     + bb0));
                    atomicAdd(&dst[1], w * (acc[i][j][half*2 + 1] + bb1));
                }
            }
        }
    }
}

// ---------------- launch -----------------------------------------------------------
extern "C" void kernel_launch(void* const* d_in, const int* in_sizes, int n_in,
                              void* d_out, int out_size)
{
    const float* x  = (const float*)d_in[0];
    const float* Wr = (const float*)d_in[1];
    const float* W1 = (const float*)d_in[2];
    const float* b1 = (const float*)d_in[3];
    const float* W2 = (const float*)d_in[4];
    const float* b2 = (const float*)d_in[5];
    float* y = (float*)d_out;

    cudaFuncSetAttribute(gemm1_mma, cudaFuncAttributeMaxDynamicSharedMemorySize, SMEM_DYN);
    cudaFuncSetAttribute(gemm2_mma, cudaFuncAttributeMaxDynamicSharedMemorySize, SMEM_DYN);

    {
        __half2 *w1h, *w2h;
        cudaGetSymbolAddress((void**)&w1h, g_w1h);
        cudaGetSymbolAddress((void**)&w2h, g_w2h);
        prep_kernel<<<PREP_BLOCKS, 256>>>(x, Wr, (const float4*)W1, (const float4*)W2,
                                          w1h, w2h, (float4*)d_out);                 // 1 (router | W-convert MLP=4 | y-zero MLP=4)
    }
    finalize_kernel<<<1, 1024>>>(y, out_size);                                       // 2 (l_aux + counts + cursor reset)
    gemm1_mma<<<dim3(ECAP/128, FD/128, NE), 256, SMEM_DYN>>>(b1);                    // 3
    gemm2_mma<<<dim3(ECAP/128, HD/128, NE), 256, SMEM_DYN>>>(b2, y);                 // 4 <- profiled
}